// round 10
// baseline (speedup 1.0000x reference)
#include <cuda_runtime.h>
#include <cstdint>

// Problem constants (match reference_code)
#define VOC_SIZE 1000000
#define EMBED_DIM 64
#define N_UPD 262144
#define N_Q (4096 * 200)  // 819200 query rows

// Scratch (allocation-free __device__ globals).
// Per-row linked list of updates:
//   g_head[row] = 1 + index of the last update hitting `row` (0 = untouched)
//   g_next[i]   = 1 + index of the previous update hitting the same row
// Fully rebuilt every replay (M0 zeros g_head; K2a writes every g_next),
// so each replay is deterministic up to fp add order.
__device__ int g_head[1 << 20];   // 4 MB (padded to power of two)
__device__ int g_next[N_UPD];     // 1 MB

typedef unsigned long long u64;

// 32-byte table load with L2 evict_last (sm_103a: modifier requires
// .v8.b32 / .v4.b64 width). Duplicate queries re-read table rows; bias them
// to stay resident in L2.
__device__ __forceinline__ void ldg_evict_last_32B(const float* p,
                                                   u64& x, u64& y, u64& z, u64& w) {
    asm("ld.global.nc.L2::evict_last.v4.b64 {%0,%1,%2,%3}, [%4];"
        : "=l"(x), "=l"(y), "=l"(z), "=l"(w) : "l"(p));
}

// Streaming store (evict-first): output is written once and never re-read.
__device__ __forceinline__ void stg_cs_32B(float* p, u64 x, u64 y, u64 z, u64 w) {
    asm volatile("st.global.cs.v4.b64 [%0], {%1,%2,%3,%4};"
                 :: "l"(p), "l"(x), "l"(y), "l"(z), "l"(w) : "memory");
}

__device__ __forceinline__ u64 pack2(float lo, float hi) {
    return ((u64)__float_as_uint(hi) << 32) | (u64)__float_as_uint(lo);
}
__device__ __forceinline__ float f_lo(u64 v) { return __uint_as_float((unsigned)v); }
__device__ __forceinline__ float f_hi(u64 v) { return __uint_as_float((unsigned)(v >> 32)); }

// M0: zero the head array (4 MB, L2-resident). 2048 blocks for enough waves
// to cover store latency (512 blocks was latency-bound at 3.7% issue).
__global__ void zero_head_kernel() {
    int t = blockIdx.x * blockDim.x + threadIdx.x;   // 0 .. 524287
    u64 z = 0ULL;
    asm volatile("st.global.b64 [%0], %1;"
                 :: "l"(&g_head[t * 2]), "l"(z) : "memory");
}

// K2a: build per-row linked lists of updates. Two independent updates per
// thread for MLP. atomicExch gives each row a race-free chain regardless of
// arrival order.
__global__ void link_kernel(const int* __restrict__ indices) {
    int t = blockIdx.x * blockDim.x + threadIdx.x;   // 0 .. N_UPD/2-1
    int i1 = t + N_UPD / 2;
    int r0 = indices[t];
    int r1 = indices[i1];
    int o0 = atomicExch(&g_head[r0], t + 1);
    int o1 = atomicExch(&g_head[r1], i1 + 1);
    g_next[t]  = o0;
    g_next[i1] = o1;
}

// Walk the update chain of one row, accumulating into the 32B quad.
__device__ __forceinline__ void add_chain(int p, int j,
                                          const float* __restrict__ upd,
                                          u64& x, u64& y, u64& z, u64& w) {
    if (!p) return;
    float4 sa = make_float4(0.f, 0.f, 0.f, 0.f);
    float4 sb = make_float4(0.f, 0.f, 0.f, 0.f);
    do {
        int i = p - 1;
        const float4* up = reinterpret_cast<const float4*>(
            &upd[(size_t)i * EMBED_DIM + j * 8]);
        float4 da = __ldg(up);
        float4 db = __ldg(up + 1);
        sa.x += da.x; sa.y += da.y; sa.z += da.z; sa.w += da.w;
        sb.x += db.x; sb.y += db.y; sb.z += db.z; sb.w += db.w;
        p = g_next[i];
    } while (p);
    x = pack2(f_lo(x) + sa.x, f_hi(x) + sa.y);
    y = pack2(f_lo(y) + sa.z, f_hi(y) + sa.w);
    z = pack2(f_lo(z) + sb.x, f_hi(z) + sb.y);
    w = pack2(f_lo(w) + sb.z, f_hi(w) + sb.w);
}

// K3: gather. out[q] = table[q] + sum over the update chain of row q.
// 8 threads per 256B row, 32B per thread; each thread handles FOUR query
// rows (i, +N_Q/4, +N_Q/2, +3N_Q/4) -> 4 independent table loads + 4 head
// loads in flight (long-scoreboard hiding). g_head/g_next are L2-hot.
// Table reads: L2 evict_last. Output: streaming stores.
__global__ void gather_kernel(const float* __restrict__ table,
                              const int* __restrict__ qs,
                              const float* __restrict__ upd,
                              float* __restrict__ out) {
    int t = blockIdx.x * blockDim.x + threadIdx.x;   // 0 .. N_Q*2-1
    int i0 = t >> 3;                                 // 0 .. N_Q/4-1
    int j  = t & 7;
    int i1 = i0 + (N_Q / 4);
    int i2 = i0 + (N_Q / 2);
    int i3 = i0 + (3 * N_Q / 4);

    int r0 = qs[i0];
    int r1 = qs[i1];
    int r2 = qs[i2];
    int r3 = qs[i3];
    size_t o0 = (size_t)r0 * EMBED_DIM + j * 8;
    size_t o1 = (size_t)r1 * EMBED_DIM + j * 8;
    size_t o2 = (size_t)r2 * EMBED_DIM + j * 8;
    size_t o3 = (size_t)r3 * EMBED_DIM + j * 8;

    u64 x0, y0, z0, w0, x1, y1, z1, w1, x2, y2, z2, w2, x3, y3, z3, w3;
    ldg_evict_last_32B(&table[o0], x0, y0, z0, w0);
    ldg_evict_last_32B(&table[o1], x1, y1, z1, w1);
    ldg_evict_last_32B(&table[o2], x2, y2, z2, w2);
    ldg_evict_last_32B(&table[o3], x3, y3, z3, w3);
    int p0 = g_head[r0];
    int p1 = g_head[r1];
    int p2 = g_head[r2];
    int p3 = g_head[r3];

    add_chain(p0, j, upd, x0, y0, z0, w0);
    add_chain(p1, j, upd, x1, y1, z1, w1);
    add_chain(p2, j, upd, x2, y2, z2, w2);
    add_chain(p3, j, upd, x3, y3, z3, w3);

    stg_cs_32B(&out[(size_t)i0 * EMBED_DIM + j * 8], x0, y0, z0, w0);
    stg_cs_32B(&out[(size_t)i1 * EMBED_DIM + j * 8], x1, y1, z1, w1);
    stg_cs_32B(&out[(size_t)i2 * EMBED_DIM + j * 8], x2, y2, z2, w2);
    stg_cs_32B(&out[(size_t)i3 * EMBED_DIM + j * 8], x3, y3, z3, w3);
}

extern "C" void kernel_launch(void* const* d_in, const int* in_sizes, int n_in,
                              void* d_out, int out_size) {
    // metadata order: kernel (f32), indices (i32), emb_update (f32), qs (i32)
    const float* table   = (const float*)d_in[0];
    const int*   indices = (const int*)d_in[1];
    const float* upd     = (const float*)d_in[2];
    const int*   qs      = (const int*)d_in[3];
    float* out = (float*)d_out;

    // M0: (1<<20) ints / 2 per thread = 524288 threads = 2048 blocks (exact)
    zero_head_kernel<<<2048, 256>>>();
    // K2a: N_UPD/2 threads = 512 blocks (exact)
    link_kernel<<<512, 256>>>(indices);
    // K3: N_Q*2 threads = 6400 blocks (exact)
    gather_kernel<<<6400, 256>>>(table, qs, upd, out);
}

// round 11
// speedup vs baseline: 1.0458x; 1.0458x over previous
#include <cuda_runtime.h>
#include <cstdint>

// Problem constants (match reference_code)
#define VOC_SIZE 1000000
#define EMBED_DIM 64
#define N_UPD 262144
#define N_Q (4096 * 200)  // 819200 query rows

// Scratch (allocation-free __device__ globals).
// Per-row linked list of updates:
//   g_head[row] = 1 + index of the last update hitting `row` (0 = untouched)
//   g_next[i]   = 1 + index of the previous update hitting the same row
// Invariant: g_head is all-zero at entry to every kernel_launch invocation
// (zero-initialized at module load; clear_head_kernel restores it at the end
// of each invocation by zeroing exactly the rows link_kernel touched).
__device__ int g_head[1 << 20];   // 4 MB (padded to power of two)
__device__ int g_next[N_UPD];     // 1 MB

typedef unsigned long long u64;

// 32-byte table load with L2 evict_last (sm_103a: modifier requires
// .v8.b32 / .v4.b64 width). Duplicate queries re-read table rows; bias them
// to stay resident in L2.
__device__ __forceinline__ void ldg_evict_last_32B(const float* p,
                                                   u64& x, u64& y, u64& z, u64& w) {
    asm("ld.global.nc.L2::evict_last.v4.b64 {%0,%1,%2,%3}, [%4];"
        : "=l"(x), "=l"(y), "=l"(z), "=l"(w) : "l"(p));
}

// Streaming store (evict-first): output is written once and never re-read.
__device__ __forceinline__ void stg_cs_32B(float* p, u64 x, u64 y, u64 z, u64 w) {
    asm volatile("st.global.cs.v4.b64 [%0], {%1,%2,%3,%4};"
                 :: "l"(p), "l"(x), "l"(y), "l"(z), "l"(w) : "memory");
}

__device__ __forceinline__ u64 pack2(float lo, float hi) {
    return ((u64)__float_as_uint(hi) << 32) | (u64)__float_as_uint(lo);
}
__device__ __forceinline__ float f_lo(u64 v) { return __uint_as_float((unsigned)v); }
__device__ __forceinline__ float f_hi(u64 v) { return __uint_as_float((unsigned)(v >> 32)); }

// K1: build per-row linked lists of updates. Requires g_head == 0 on entry
// (see invariant above). Two independent updates per thread for MLP.
__global__ void link_kernel(const int* __restrict__ indices) {
    int t = blockIdx.x * blockDim.x + threadIdx.x;   // 0 .. N_UPD/2-1
    int i1 = t + N_UPD / 2;
    int r0 = indices[t];
    int r1 = indices[i1];
    int o0 = atomicExch(&g_head[r0], t + 1);
    int o1 = atomicExch(&g_head[r1], i1 + 1);
    g_next[t]  = o0;
    g_next[i1] = o1;
}

// K3 (cleanup): restore the all-zero g_head invariant by clearing exactly
// the rows link_kernel touched. Runs after the gather (last reader).
// Duplicate indices -> redundant zero stores, harmless.
__global__ void clear_head_kernel(const int* __restrict__ indices) {
    int t = blockIdx.x * blockDim.x + threadIdx.x;   // 0 .. N_UPD/2-1
    int i1 = t + N_UPD / 2;
    int r0 = indices[t];
    int r1 = indices[i1];
    g_head[r0] = 0;
    g_head[r1] = 0;
}

// K2: gather. out[q] = table[q] + sum over the update chain of row q.
// 8 threads per 256B row, 32B per thread; each thread handles TWO query rows
// (i, i+N_Q/2) for MLP (4-way was a measured regression: reg pressure +
// serialized chain tails). g_head/g_next are small and L2-hot. Table reads:
// L2 evict_last. Output: streaming stores.
__global__ void gather_kernel(const float* __restrict__ table,
                              const int* __restrict__ qs,
                              const float* __restrict__ upd,
                              float* __restrict__ out) {
    int t = blockIdx.x * blockDim.x + threadIdx.x;   // 0 .. N_Q*4-1
    int i0 = t >> 3;
    int j  = t & 7;
    int i1 = i0 + (N_Q / 2);

    int r0 = qs[i0];
    int r1 = qs[i1];
    size_t o0 = (size_t)r0 * EMBED_DIM + j * 8;
    size_t o1 = (size_t)r1 * EMBED_DIM + j * 8;

    u64 x0, y0, z0, w0, x1, y1, z1, w1;
    ldg_evict_last_32B(&table[o0], x0, y0, z0, w0);
    ldg_evict_last_32B(&table[o1], x1, y1, z1, w1);
    int p0 = g_head[r0];
    int p1 = g_head[r1];

    if (p0) {
        float4 sa = make_float4(0.f, 0.f, 0.f, 0.f);
        float4 sb = make_float4(0.f, 0.f, 0.f, 0.f);
        do {
            int i = p0 - 1;
            const float4* up = reinterpret_cast<const float4*>(
                &upd[(size_t)i * EMBED_DIM + j * 8]);
            float4 da = __ldg(up);
            float4 db = __ldg(up + 1);
            sa.x += da.x; sa.y += da.y; sa.z += da.z; sa.w += da.w;
            sb.x += db.x; sb.y += db.y; sb.z += db.z; sb.w += db.w;
            p0 = g_next[i];
        } while (p0);
        x0 = pack2(f_lo(x0) + sa.x, f_hi(x0) + sa.y);
        y0 = pack2(f_lo(y0) + sa.z, f_hi(y0) + sa.w);
        z0 = pack2(f_lo(z0) + sb.x, f_hi(z0) + sb.y);
        w0 = pack2(f_lo(w0) + sb.z, f_hi(w0) + sb.w);
    }
    if (p1) {
        float4 sa = make_float4(0.f, 0.f, 0.f, 0.f);
        float4 sb = make_float4(0.f, 0.f, 0.f, 0.f);
        do {
            int i = p1 - 1;
            const float4* up = reinterpret_cast<const float4*>(
                &upd[(size_t)i * EMBED_DIM + j * 8]);
            float4 da = __ldg(up);
            float4 db = __ldg(up + 1);
            sa.x += da.x; sa.y += da.y; sa.z += da.z; sa.w += da.w;
            sb.x += db.x; sb.y += db.y; sb.z += db.z; sb.w += db.w;
            p1 = g_next[i];
        } while (p1);
        x1 = pack2(f_lo(x1) + sa.x, f_hi(x1) + sa.y);
        y1 = pack2(f_lo(y1) + sa.z, f_hi(y1) + sa.w);
        z1 = pack2(f_lo(z1) + sb.x, f_hi(z1) + sb.y);
        w1 = pack2(f_lo(w1) + sb.z, f_hi(w1) + sb.w);
    }

    stg_cs_32B(&out[(size_t)i0 * EMBED_DIM + j * 8], x0, y0, z0, w0);
    stg_cs_32B(&out[(size_t)i1 * EMBED_DIM + j * 8], x1, y1, z1, w1);
}

extern "C" void kernel_launch(void* const* d_in, const int* in_sizes, int n_in,
                              void* d_out, int out_size) {
    // metadata order: kernel (f32), indices (i32), emb_update (f32), qs (i32)
    const float* table   = (const float*)d_in[0];
    const int*   indices = (const int*)d_in[1];
    const float* upd     = (const float*)d_in[2];
    const int*   qs      = (const int*)d_in[3];
    float* out = (float*)d_out;

    // K1: N_UPD/2 threads = 512 blocks (exact). g_head all-zero on entry.
    link_kernel<<<512, 256>>>(indices);
    // K2: N_Q*4 threads = 12800 blocks (exact)
    gather_kernel<<<12800, 256>>>(table, qs, upd, out);
    // K3: restore g_head == 0 for the next invocation/replay
    clear_head_kernel<<<512, 256>>>(indices);
}

// round 12
// speedup vs baseline: 1.0507x; 1.0047x over previous
#include <cuda_runtime.h>
#include <cstdint>

// Problem constants (match reference_code)
#define VOC_SIZE 1000000
#define EMBED_DIM 64
#define N_UPD 262144
#define N_Q (4096 * 200)  // 819200 query rows

// Scratch (allocation-free __device__ globals).
// Per-row linked list of updates:
//   g_head[row] = 1 + index of the last update hitting `row` (0 = untouched)
//   g_next[i]   = 1 + index of the previous update hitting the same row
// Invariant: g_head is all-zero at entry to every kernel_launch invocation
// (zero-initialized at module load; clear_head_kernel restores it at the end
// of each invocation by zeroing exactly the rows link_kernel touched).
__device__ int g_head[1 << 20];   // 4 MB (padded to power of two)
__device__ int g_next[N_UPD];     // 1 MB

typedef unsigned long long u64;

// 32-byte table load with L2 evict_last (sm_103a: modifier requires
// .v8.b32 / .v4.b64 width). Duplicate queries re-read table rows; bias them
// to stay resident in L2.
__device__ __forceinline__ void ldg_evict_last_32B(const float* p,
                                                   u64& x, u64& y, u64& z, u64& w) {
    asm("ld.global.nc.L2::evict_last.v4.b64 {%0,%1,%2,%3}, [%4];"
        : "=l"(x), "=l"(y), "=l"(z), "=l"(w) : "l"(p));
}

// Streaming store (evict-first): output is written once and never re-read.
__device__ __forceinline__ void stg_cs_32B(float* p, u64 x, u64 y, u64 z, u64 w) {
    asm volatile("st.global.cs.v4.b64 [%0], {%1,%2,%3,%4};"
                 :: "l"(p), "l"(x), "l"(y), "l"(z), "l"(w) : "memory");
}

__device__ __forceinline__ u64 pack2(float lo, float hi) {
    return ((u64)__float_as_uint(hi) << 32) | (u64)__float_as_uint(lo);
}
__device__ __forceinline__ float f_lo(u64 v) { return __uint_as_float((unsigned)v); }
__device__ __forceinline__ float f_hi(u64 v) { return __uint_as_float((unsigned)(v >> 32)); }

// K1: build per-row linked lists of updates. Requires g_head == 0 on entry.
// ONE update per thread, 2x the warps of the 2-per-thread version: the
// kernel is ATOMG-latency-bound (occ 34%, issue 2.2% measured), so the win
// is more outstanding atomics, not fewer instructions.
__global__ void link_kernel(const int* __restrict__ indices) {
    int i = blockIdx.x * blockDim.x + threadIdx.x;   // 0 .. N_UPD-1
    int r = indices[i];
    int o = atomicExch(&g_head[r], i + 1);
    g_next[i] = o;
}

// K3 (cleanup): restore the all-zero g_head invariant by clearing exactly
// the rows link_kernel touched. Runs after the gather (last reader).
// Duplicate indices -> redundant zero stores, harmless.
__global__ void clear_head_kernel(const int* __restrict__ indices) {
    int i = blockIdx.x * blockDim.x + threadIdx.x;   // 0 .. N_UPD-1
    g_head[indices[i]] = 0;
}

// K2: gather. out[q] = table[q] + sum over the update chain of row q.
// 8 threads per 256B row, 32B per thread; each thread handles TWO query rows
// (i, i+N_Q/2) for MLP (4-way was a measured regression: reg pressure +
// serialized chain tails). g_head/g_next are small and L2-hot. Table reads:
// L2 evict_last. Output: streaming stores.
__global__ void gather_kernel(const float* __restrict__ table,
                              const int* __restrict__ qs,
                              const float* __restrict__ upd,
                              float* __restrict__ out) {
    int t = blockIdx.x * blockDim.x + threadIdx.x;   // 0 .. N_Q*4-1
    int i0 = t >> 3;
    int j  = t & 7;
    int i1 = i0 + (N_Q / 2);

    int r0 = qs[i0];
    int r1 = qs[i1];
    size_t o0 = (size_t)r0 * EMBED_DIM + j * 8;
    size_t o1 = (size_t)r1 * EMBED_DIM + j * 8;

    u64 x0, y0, z0, w0, x1, y1, z1, w1;
    ldg_evict_last_32B(&table[o0], x0, y0, z0, w0);
    ldg_evict_last_32B(&table[o1], x1, y1, z1, w1);
    int p0 = g_head[r0];
    int p1 = g_head[r1];

    if (p0) {
        float4 sa = make_float4(0.f, 0.f, 0.f, 0.f);
        float4 sb = make_float4(0.f, 0.f, 0.f, 0.f);
        do {
            int i = p0 - 1;
            const float4* up = reinterpret_cast<const float4*>(
                &upd[(size_t)i * EMBED_DIM + j * 8]);
            float4 da = __ldg(up);
            float4 db = __ldg(up + 1);
            sa.x += da.x; sa.y += da.y; sa.z += da.z; sa.w += da.w;
            sb.x += db.x; sb.y += db.y; sb.z += db.z; sb.w += db.w;
            p0 = g_next[i];
        } while (p0);
        x0 = pack2(f_lo(x0) + sa.x, f_hi(x0) + sa.y);
        y0 = pack2(f_lo(y0) + sa.z, f_hi(y0) + sa.w);
        z0 = pack2(f_lo(z0) + sb.x, f_hi(z0) + sb.y);
        w0 = pack2(f_lo(w0) + sb.z, f_hi(w0) + sb.w);
    }
    if (p1) {
        float4 sa = make_float4(0.f, 0.f, 0.f, 0.f);
        float4 sb = make_float4(0.f, 0.f, 0.f, 0.f);
        do {
            int i = p1 - 1;
            const float4* up = reinterpret_cast<const float4*>(
                &upd[(size_t)i * EMBED_DIM + j * 8]);
            float4 da = __ldg(up);
            float4 db = __ldg(up + 1);
            sa.x += da.x; sa.y += da.y; sa.z += da.z; sa.w += da.w;
            sb.x += db.x; sb.y += db.y; sb.z += db.z; sb.w += db.w;
            p1 = g_next[i];
        } while (p1);
        x1 = pack2(f_lo(x1) + sa.x, f_hi(x1) + sa.y);
        y1 = pack2(f_lo(y1) + sa.z, f_hi(y1) + sa.w);
        z1 = pack2(f_lo(z1) + sb.x, f_hi(z1) + sb.y);
        w1 = pack2(f_lo(w1) + sb.z, f_hi(w1) + sb.w);
    }

    stg_cs_32B(&out[(size_t)i0 * EMBED_DIM + j * 8], x0, y0, z0, w0);
    stg_cs_32B(&out[(size_t)i1 * EMBED_DIM + j * 8], x1, y1, z1, w1);
}

extern "C" void kernel_launch(void* const* d_in, const int* in_sizes, int n_in,
                              void* d_out, int out_size) {
    // metadata order: kernel (f32), indices (i32), emb_update (f32), qs (i32)
    const float* table   = (const float*)d_in[0];
    const int*   indices = (const int*)d_in[1];
    const float* upd     = (const float*)d_in[2];
    const int*   qs      = (const int*)d_in[3];
    float* out = (float*)d_out;

    // K1: N_UPD threads = 1024 blocks (exact). g_head all-zero on entry.
    link_kernel<<<1024, 256>>>(indices);
    // K2: N_Q*4 threads = 12800 blocks (exact)
    gather_kernel<<<12800, 256>>>(table, qs, upd, out);
    // K3: restore g_head == 0 for the next invocation/replay
    clear_head_kernel<<<1024, 256>>>(indices);
}